// round 9
// baseline (speedup 1.0000x reference)
#include <cuda_runtime.h>
#include <cstdint>

#define NIDS   1000000
#define ZCH    400000
#define DIM    128
#define TOTAL  (2 * NIDS)
#define HASHSZ 4000000
#define WPB    8              // warps per block (256 threads)
#define QCAP   224            // worst case: 7 chunks * 32 ids, all cold

// Static scratch (no allocations allowed). Zero-initialized at module load.
// inv maps store slot+1; 0 means "unmatched" -> collision slot ZCH-1.
// Entries are rewritten identically by scatter_kernel on every launch.
__device__ double   g_acc;
__device__ unsigned g_done;
__device__ int      g_inv0[HASHSZ];
__device__ int      g_inv1[HASHSZ];

// Table values < 4M < 2^22: if the buffer is int64, the odd 32-bit words of
// the first entries are all 0; sorted random int32 data -> essentially never.
__device__ __forceinline__ bool sniff_is64(const unsigned* __restrict__ w) {
    return (w[1] | w[3] | w[5] | w[7]) == 0u;
}

// ---------------------------------------------------------------------------
// 1) Scatter slot+1 into the inverse maps. lower_bound semantics: first
//    occurrence wins for duplicates (branch on sorted neighbor, no atomics).
// ---------------------------------------------------------------------------
__global__ __launch_bounds__(256) void scatter_kernel(
    const void* __restrict__ m0v, const void* __restrict__ m1v)
{
    const int tid = blockIdx.x * blockDim.x + threadIdx.x;
    if (tid >= 2 * ZCH) return;
    const int feat = (tid >= ZCH) ? 1 : 0;
    const int j    = feat ? (tid - ZCH) : tid;
    const void* mv = feat ? m1v : m0v;
    int* inv       = feat ? g_inv1 : g_inv0;

    const bool is64 = sniff_is64((const unsigned*)m0v);
    int id, prev = -1;
    if (is64) {
        const long long* m = (const long long*)mv;
        id = (int)m[j];
        if (j > 0) prev = (int)m[j - 1];
    } else {
        const int* m = (const int*)mv;
        id = m[j];
        if (j > 0) prev = m[j - 1];
    }
    if (j == 0 || prev != id) inv[id] = j + 1;
}

// ---------------------------------------------------------------------------
// 2) Main, two-phase:
//    Phase 1: depth-2 pipelined id->inv streaming; slots written to out;
//             cold (slot | feat<<20) entries compacted into a per-warp
//             SMEM queue (no gather in the latency-critical loop).
//    Phase 2: each warp drains its queue 4 rows at a time -- 4 independent
//             row loads in flight before any consumption (gather latency/4).
//    Hot-row contribution folded algebraically; last-block finalize.
// ---------------------------------------------------------------------------
__global__ __launch_bounds__(256) void sparse_arch_kernel(
    const void* __restrict__ ids0v, const void* __restrict__ ids1v,
    const void* __restrict__ m0v,
    const float* __restrict__ e0,   const float* __restrict__ e1,
    float* __restrict__ out)
{
    __shared__ double blk_acc;
    __shared__ int    queue[WPB * QCAP];
    if (threadIdx.x == 0) blk_acc = 0.0;
    __syncthreads();

    const int  lane = threadIdx.x & 31;
    const int  wib  = threadIdx.x >> 5;            // warp in block
    const int  wg   = blockIdx.x * WPB + wib;
    const int  nw   = gridDim.x * WPB;
    const int  step = nw * 32;
    const bool is64 = sniff_is64((const unsigned*)m0v);
    int* __restrict__ q = queue + wib * QCAP;

    // Streaming id load for chunk at 'b' (clamped to 0 when OOB; result
    // unused in that case). feat is warp-uniform because NIDS % 32 == 0.
    auto load_id = [&](int b, int& feat_o) -> int {
        const int bb  = (b < TOTAL) ? b : 0;
        const int idx = bb + lane;
        const int f   = (idx >= NIDS) ? 1 : 0;
        const int i   = idx - (f ? NIDS : 0);
        feat_o = f;
        if (is64)  // little-endian low word; values < 2^22
            return __ldcs((const int*)(f ? ids1v : ids0v) + (i << 1));
        else
            return __ldcs((const int*)(f ? ids1v : ids0v) + i);
    };

    // Collision-row sums (broadcast to all lanes), computed once per warp.
    const float4 h0 = ((const float4*)(e0 + (size_t)(ZCH - 1) * DIM))[lane];
    const float4 h1 = ((const float4*)(e1 + (size_t)(ZCH - 1) * DIM))[lane];
    float hs0 = (h0.x + h0.y) + (h0.z + h0.w);
    float hs1 = (h1.x + h1.y) + (h1.z + h1.w);
    #pragma unroll
    for (int o = 16; o > 0; o >>= 1) {
        hs0 += __shfl_xor_sync(0xffffffffu, hs0, o);
        hs1 += __shfl_xor_sync(0xffffffffu, hs1, o);
    }

    long long hot0 = 0, hot1 = 0;
    int qn = 0;                                   // queue length (uniform)

    // ---------------- Phase 1: remap + slot output + queue cold rows ------
    // Prologue (every warp has >= 1 chunk: step = 303104 < TOTAL).
    int featA, cellA;          // chunk n:   inv result pending
    int featB, idB;            // chunk n+1: id loaded, inv not yet issued
    {
        int idA = load_id(wg * 32, featA);
        cellA = __ldcg((featA ? g_inv1 : g_inv0) + idA);
        idB   = load_id(wg * 32 + step, featB);
    }

    for (int base = wg * 32; base < TOTAL; base += step) {
        // Issue inv(n+1) from the already-loaded idB.
        int cellB = 0;
        if (base + step < TOTAL)
            cellB = __ldcg((featB ? g_inv1 : g_inv0) + idB);

        // Issue id(n+2).
        int featC;
        const int idC = load_id(base + 2 * step, featC);

        // ---- Process chunk n ----
        const int slot = cellA ? (cellA - 1) : (ZCH - 1);
        __stcs(out + 1 + base + lane, (float)slot);

        const unsigned hotm  = __ballot_sync(0xffffffffu, slot == ZCH - 1);
        const unsigned coldm = ~hotm;
        if (featA) hot1 += __popc(hotm); else hot0 += __popc(hotm);

        // Compact cold slots into the per-warp queue.
        if (coldm & (1u << lane)) {
            const int rank = __popc(coldm & ((1u << lane) - 1u));
            q[qn + rank] = slot | (featA << 20);   // slot < 2^19
        }
        qn += __popc(coldm);

        // Rotate pipeline stages.
        featA = featB; cellA = cellB;
        featB = featC; idB   = idC;
    }

    // ---------------- Phase 2: drain queue, 4 rows in flight --------------
    float s0 = 0.f, s1 = 0.f, s2 = 0.f, s3 = 0.f;
    int k = 0;
    for (; k + 4 <= qn; k += 4) {
        const int q0 = q[k], q1 = q[k + 1], q2 = q[k + 2], q3 = q[k + 3];
        const float* r0 = ((q0 >> 20) ? e1 : e0) + (size_t)(q0 & 0xFFFFF) * DIM;
        const float* r1 = ((q1 >> 20) ? e1 : e0) + (size_t)(q1 & 0xFFFFF) * DIM;
        const float* r2 = ((q2 >> 20) ? e1 : e0) + (size_t)(q2 & 0xFFFFF) * DIM;
        const float* r3 = ((q3 >> 20) ? e1 : e0) + (size_t)(q3 & 0xFFFFF) * DIM;
        const float4 a = __ldcs((const float4*)r0 + lane);
        const float4 b = __ldcs((const float4*)r1 + lane);
        const float4 c = __ldcs((const float4*)r2 + lane);
        const float4 d = __ldcs((const float4*)r3 + lane);
        s0 += (a.x + a.y) + (a.z + a.w);
        s1 += (b.x + b.y) + (b.z + b.w);
        s2 += (c.x + c.y) + (c.z + c.w);
        s3 += (d.x + d.y) + (d.z + d.w);
    }
    for (; k < qn; ++k) {
        const int qe = q[k];
        const float* r = ((qe >> 20) ? e1 : e0) + (size_t)(qe & 0xFFFFF) * DIM;
        const float4 a = __ldcs((const float4*)r + lane);
        s0 += (a.x + a.y) + (a.z + a.w);
    }

    float s = (s0 + s1) + (s2 + s3);
    #pragma unroll
    for (int o = 16; o > 0; o >>= 1)
        s += __shfl_down_sync(0xffffffffu, s, o);

    if (lane == 0) {
        const double t = (double)s
                       + (double)hot0 * (double)hs0
                       + (double)hot1 * (double)hs1;
        atomicAdd(&blk_acc, t);
    }
    __syncthreads();

    if (threadIdx.x == 0) {
        atomicAdd(&g_acc, blk_acc);
        __threadfence();
        const unsigned done = atomicAdd(&g_done, 1u);
        if (done == gridDim.x - 1) {              // last block finalizes
            const double total = atomicAdd(&g_acc, 0.0);
            out[0] = (float)(total / ((double)TOTAL * (double)DIM));
            g_acc  = 0.0;                          // reset for next replay
            g_done = 0u;
        }
    }
}

// ---------------------------------------------------------------------------
// Launch: 2 kernels, graph-capturable, allocation-free.
// Inputs (metadata order): ids_0, ids_1, mch_ids_0, mch_ids_1, emb_0, emb_1
// Output: [loss, remapped_0 (1M), remapped_1 (1M)] as float32.
// ---------------------------------------------------------------------------
extern "C" void kernel_launch(void* const* d_in, const int* in_sizes, int n_in,
                              void* d_out, int out_size)
{
    const void*  ids0 = d_in[0];
    const void*  ids1 = d_in[1];
    const void*  m0   = d_in[2];
    const void*  m1   = d_in[3];
    const float* e0   = (const float*)d_in[4];
    const float* e1   = (const float*)d_in[5];
    float* out = (float*)d_out;

    const int threads = 256;
    scatter_kernel<<<(2 * ZCH + threads - 1) / threads, threads>>>(m0, m1);
    sparse_arch_kernel<<<148 * 8, threads>>>(ids0, ids1, m0, e0, e1, out);
}